// round 2
// baseline (speedup 1.0000x reference)
#include <cuda_runtime.h>

// Problem constants (fixed shapes: B=32, C=68, H=128, W=128)
#define H 128
#define W 128
#define TILE 32                 // output rows per block
#define SROWS (TILE + 2)        // +1 halo row each side
#define TILES_PER_PLANE (H / TILE)
#define NPLANES (32 * 68)
#define NBLOCKS (NPLANES * TILES_PER_PLANE)   // 8704

// Loss constants
#define OMEGA 14.0f
#define ALPHA 2.1f
#define THETA 0.5f
#define MASK_THRESHOLD 0.2f
// mask value = MASK_W + 1 = 11, else 1

__device__ float g_partials[NBLOCKS];

__global__ __launch_bounds__(128, 8)
void awing_main_kernel(const float* __restrict__ pred,
                       const float* __restrict__ targ)
{
    __shared__ float s[SROWS * W];   // 34 * 128 * 4B = 17 KB

    const int bx      = blockIdx.x;
    const int plane   = bx >> 2;                 // / TILES_PER_PLANE
    const int rowBase = (bx & 3) * TILE;
    const int tid     = threadIdx.x;

    const float* tp = targ + (size_t)plane * (H * W);
    const float* pp = pred + (size_t)plane * (H * W);

    // ---- Cooperative smem fill of target rows [rowBase-1, rowBase+TILE], clamped ----
    // Each float4 index i -> row r = i>>5 (0..33), col4 = i&31. smem layout is linear.
    #pragma unroll
    for (int i = tid; i < SROWS * (W / 4); i += 128) {
        int r = i >> 5;
        int g = rowBase - 1 + r;
        g = max(0, min(H - 1, g));
        float4 v = *reinterpret_cast<const float4*>(tp + g * W + ((i & 31) << 2));
        reinterpret_cast<float4*>(s)[i] = v;
    }
    __syncthreads();

    const int c  = tid;                          // one column per thread
    const int cl = (c > 0)     ? c - 1 : 0;      // symmetric pad == clamp for pad=1
    const int cr = (c < W - 1) ? c + 1 : W - 1;

    // Rolling horizontal max (separable 3x3 dilation)
    float hm0 = fmaxf(fmaxf(s[cl],     s[c]),     s[cr]);
    float hm1 = fmaxf(fmaxf(s[W + cl], s[W + c]), s[W + cr]);

    float acc = 0.0f;

    #pragma unroll 4
    for (int lr = 0; lr < TILE; lr++) {
        const float* row2 = s + (lr + 2) * W;
        float hm2 = fmaxf(fmaxf(row2[cl], row2[c]), row2[cr]);
        float dil = fmaxf(fmaxf(hm0, hm1), hm2);

        float y = s[(lr + 1) * W + c];
        float p = __ldg(pp + (rowBase + lr) * W + c);

        float ay   = ALPHA - y;                  // in (1.1, 2.1]
        float diff = fabsf(p - y);

        float loss;
        if (diff < THETA) {
            // omega * log1p((diff/eps)^ay), eps = 1
            // diff^ay = exp2(ay * log2(diff)); diff==0 -> exp2(-inf) = 0 (correct)
            float lp = exp2f(ay * __log2f(diff));
            loss = OMEGA * __logf(1.0f + lp);
        } else {
            // pow_t = 0.5^ay = exp2(-ay); pow_tm1 = 2*pow_t
            float pt = exp2f(-ay);
            float A  = 28.0f * ay * pt / (1.0f + pt);   // omega*(1/(1+pt))*ay*2pt
            float C  = THETA * A - OMEGA * __logf(1.0f + pt);
            loss = A * diff - C;
        }

        float m = (dil > MASK_THRESHOLD) ? 11.0f : 1.0f;
        acc += loss * m;

        hm0 = hm1;
        hm1 = hm2;
    }

    // ---- Block reduction (deterministic, no atomics) ----
    #pragma unroll
    for (int o = 16; o; o >>= 1)
        acc += __shfl_down_sync(0xffffffffu, acc, o);

    __shared__ float ws[4];
    if ((tid & 31) == 0) ws[tid >> 5] = acc;
    __syncthreads();
    if (tid == 0)
        g_partials[bx] = (ws[0] + ws[1]) + (ws[2] + ws[3]);
}

__global__ __launch_bounds__(256)
void awing_final_kernel(float* __restrict__ out, long long n)
{
    __shared__ double sd[8];
    double a = 0.0;
    for (int i = threadIdx.x; i < NBLOCKS; i += 256)
        a += (double)g_partials[i];

    #pragma unroll
    for (int o = 16; o; o >>= 1)
        a += __shfl_down_sync(0xffffffffu, a, o);

    if ((threadIdx.x & 31) == 0) sd[threadIdx.x >> 5] = a;
    __syncthreads();
    if (threadIdx.x == 0) {
        double t = 0.0;
        #pragma unroll
        for (int i = 0; i < 8; i++) t += sd[i];
        out[0] = (float)(t / (double)n);
    }
}

extern "C" void kernel_launch(void* const* d_in, const int* in_sizes, int n_in,
                              void* d_out, int out_size)
{
    const float* pred = (const float*)d_in[0];   // prediction
    const float* targ = (const float*)d_in[1];   // target
    long long n = (long long)in_sizes[0];        // 35651584

    awing_main_kernel<<<NBLOCKS, 128>>>(pred, targ);
    awing_final_kernel<<<1, 256>>>((float*)d_out, n);
}

// round 3
// speedup vs baseline: 2.5587x; 2.5587x over previous
#include <cuda_runtime.h>

// Fixed shapes: B=32, C=68, H=128, W=128
#define H 128
#define W 128
#define TILE 64                      // output rows per block
#define SROWS (TILE + 2)             // +1 halo row each side
#define TILES_PER_PLANE (H / TILE)   // 2
#define NPLANES (32 * 68)            // 2176
#define NBLOCKS (NPLANES * TILES_PER_PLANE)  // 4352

#define OMEGA 14.0f
#define THETA 0.5f
#define MASK_THRESHOLD 0.2f
#define LN2 0.6931471805599453f

__device__ float g_partials[NBLOCKS];

__device__ __forceinline__ float ex2a(float x){ float r; asm("ex2.approx.ftz.f32 %0,%1;" : "=f"(r) : "f"(x)); return r; }
__device__ __forceinline__ float lg2a(float x){ float r; asm("lg2.approx.ftz.f32 %0,%1;" : "=f"(r) : "f"(x)); return r; }
__device__ __forceinline__ float rcpa(float x){ float r; asm("rcp.approx.ftz.f32 %0,%1;" : "=f"(r) : "f"(x)); return r; }

// horizontal 3-max over 4 columns: v = cols [4c..4c+3], l = col 4c-1, r = col 4c+4
__device__ __forceinline__ float4 hmax4(float4 v, float l, float r) {
    float4 h;
    h.x = fmaxf(l,   fmaxf(v.x, v.y));
    h.y = fmaxf(v.x, fmaxf(v.y, v.z));
    h.z = fmaxf(v.y, fmaxf(v.z, v.w));
    h.w = fmaxf(fmaxf(v.z, v.w), r);
    return h;
}

// unified AWing loss for one element (branchless, exact for both branches):
//   t = min(diff, theta);  x = t^ay  (== (diff)^ay in branch A, == 0.5^ay in branch B)
//   loss = omega*ln(1+x) + 2*omega*ay*x/(1+x) * max(diff-theta, 0)
__device__ __forceinline__ float awing_elem(float p, float y) {
    float ay   = 2.1f - y;
    float diff = fabsf(p - y);
    float t    = fminf(diff, THETA);
    float x    = ex2a(ay * lg2a(t));
    float l1   = lg2a(1.0f + x) * LN2;
    float dm   = fmaxf(diff - THETA, 0.0f);
    return OMEGA * l1 + 28.0f * ay * x * rcpa(1.0f + x) * dm;
}

__global__ __launch_bounds__(256)
void awing_main_kernel(const float* __restrict__ pred,
                       const float* __restrict__ targ)
{
    __shared__ float s[SROWS * W];     // 66*128*4 = 33792 B
    __shared__ float ws[8];

    const int bx      = blockIdx.x;
    const int plane   = bx >> 1;
    const int rowBase = (bx & 1) * TILE;
    const int tid     = threadIdx.x;
    const int tx      = tid & 31;      // column group: cols [4tx .. 4tx+3]
    const int ty      = tid >> 5;      // row stripe: rows [ty*8 .. ty*8+7]

    const float* tp = targ + (size_t)plane * (H * W);
    const float* pp = pred + (size_t)plane * (H * W);

    // ---- fill smem rows [rowBase-1 .. rowBase+TILE] (clamped) as float4 ----
    #pragma unroll
    for (int i = tid; i < SROWS * (W / 4); i += 256) {
        int r = i >> 5;
        int g = rowBase - 1 + r;
        g = max(0, min(H - 1, g));
        reinterpret_cast<float4*>(s)[i] =
            *reinterpret_cast<const float4*>(tp + g * W + ((i & 31) << 2));
    }
    __syncthreads();

    const int c0 = tx << 2;
    const int cl = max(c0 - 1, 0);
    const int cr = min(c0 + 4, W - 1);
    const int lr0 = ty * 8;            // first output row (tile-local)

    // ring init: smem row sr holds tile row sr-1
    // hm0 = hmax of tile row lr0-1 (smem row lr0); hm1 & v1 = tile row lr0 (smem row lr0+1)
    float4 v0 = *reinterpret_cast<const float4*>(s + lr0 * W + c0);
    float4 hm0 = hmax4(v0, s[lr0 * W + cl], s[lr0 * W + cr]);
    float4 v1 = *reinterpret_cast<const float4*>(s + (lr0 + 1) * W + c0);
    float4 hm1 = hmax4(v1, s[(lr0 + 1) * W + cl], s[(lr0 + 1) * W + cr]);

    float acc = 0.0f;
    const float* prow = pp + (rowBase + lr0) * W + c0;

    #pragma unroll 4
    for (int k = 0; k < 8; k++) {
        const int sr2 = (lr0 + k + 2) * W;
        float4 v2  = *reinterpret_cast<const float4*>(s + sr2 + c0);
        float4 hm2 = hmax4(v2, s[sr2 + cl], s[sr2 + cr]);

        float4 p = *reinterpret_cast<const float4*>(prow);
        prow += W;

        float dx = fmaxf(fmaxf(hm0.x, hm1.x), hm2.x);
        float dy = fmaxf(fmaxf(hm0.y, hm1.y), hm2.y);
        float dz = fmaxf(fmaxf(hm0.z, hm1.z), hm2.z);
        float dw = fmaxf(fmaxf(hm0.w, hm1.w), hm2.w);

        float lx = awing_elem(p.x, v1.x);
        float ly = awing_elem(p.y, v1.y);
        float lz = awing_elem(p.z, v1.z);
        float lw = awing_elem(p.w, v1.w);

        acc += lx * ((dx > MASK_THRESHOLD) ? 11.0f : 1.0f);
        acc += ly * ((dy > MASK_THRESHOLD) ? 11.0f : 1.0f);
        acc += lz * ((dz > MASK_THRESHOLD) ? 11.0f : 1.0f);
        acc += lw * ((dw > MASK_THRESHOLD) ? 11.0f : 1.0f);

        hm0 = hm1; hm1 = hm2; v1 = v2;
    }

    // ---- deterministic block reduction ----
    #pragma unroll
    for (int o = 16; o; o >>= 1)
        acc += __shfl_down_sync(0xffffffffu, acc, o);
    if (tx == 0) ws[ty] = acc;
    __syncthreads();
    if (tid == 0) {
        float t = ((ws[0] + ws[1]) + (ws[2] + ws[3]))
                + ((ws[4] + ws[5]) + (ws[6] + ws[7]));
        g_partials[bx] = t;
    }
}

__global__ __launch_bounds__(256)
void awing_final_kernel(float* __restrict__ out, long long n)
{
    __shared__ double sd[8];
    double a = 0.0;
    const float4* gp4 = reinterpret_cast<const float4*>(g_partials);
    #pragma unroll
    for (int i = threadIdx.x; i < NBLOCKS / 4; i += 256) {
        float4 v = gp4[i];
        a += (double)v.x + (double)v.y + (double)v.z + (double)v.w;
    }
    #pragma unroll
    for (int o = 16; o; o >>= 1)
        a += __shfl_down_sync(0xffffffffu, a, o);
    if ((threadIdx.x & 31) == 0) sd[threadIdx.x >> 5] = a;
    __syncthreads();
    if (threadIdx.x == 0) {
        double t = ((sd[0] + sd[1]) + (sd[2] + sd[3]))
                 + ((sd[4] + sd[5]) + (sd[6] + sd[7]));
        out[0] = (float)(t / (double)n);
    }
}

extern "C" void kernel_launch(void* const* d_in, const int* in_sizes, int n_in,
                              void* d_out, int out_size)
{
    const float* pred = (const float*)d_in[0];
    const float* targ = (const float*)d_in[1];
    long long n = (long long)in_sizes[0];   // 35651584

    awing_main_kernel<<<NBLOCKS, 256>>>(pred, targ);
    awing_final_kernel<<<1, 256>>>((float*)d_out, n);
}